// round 10
// baseline (speedup 1.0000x reference)
#include <cuda_runtime.h>
#include <math.h>

#define BB 128
#define TT 512
#define ENC 512
#define HHD 512
#define AA 18
#define MM (BB*TT)
#define G4 (4*HHD)

#define N_LOGITS ((size_t)MM*AA)
#define OFF_LOGITS ((size_t)0)
#define OFF_VALUES (N_LOGITS)
#define OFF_HT (OFF_VALUES + (size_t)MM)
#define OFF_CT (OFF_HT + (size_t)BB*HHD)
#define OFF_AR (OFF_CT + (size_t)BB*HHD)
#define OFF_TAR (OFF_AR + 1)
#define NGATE ((size_t)MM*HHD)
#define OFF_IG (OFF_TAR + 1)
#define OFF_FG (OFF_IG + NGATE)
#define OFF_GG (OFF_FG + NGATE)
#define OFF_OG (OFF_GG + NGATE)

__device__ __align__(16) float g_enc1[(size_t)MM*ENC];   // enc1; later reused as LSTM out (B,T,H)
__device__ __align__(16) float g_enc2[(size_t)MM*ENC];
__device__ __align__(16) float g_xg[(size_t)MM*G4];
__device__ __align__(16) float g_h[2][BB*HHD];
#define LOSS_BLOCKS 2048
__device__ double g_part[2][LOSS_BLOCKS];
__device__ unsigned g_arrive;
__device__ unsigned g_release;

__device__ __forceinline__ float sigf(float x){ return 1.f/(1.f+expf(-x)); }
__device__ __forceinline__ unsigned long long f2dup(float x){
    unsigned long long r; asm("mov.b64 %0, {%1, %1};" : "=l"(r) : "r"(__float_as_uint(x))); return r;
}
__device__ __forceinline__ void fma2(unsigned long long& d, unsigned long long a, unsigned long long b){
    asm("fma.rn.f32x2 %0, %1, %2, %0;" : "+l"(d) : "l"(a), "l"(b));
}
__device__ __forceinline__ void unpack2(unsigned long long v, float& lo, float& hi){
    unsigned l,h; asm("mov.b64 {%0, %1}, %2;" : "=r"(l), "=r"(h) : "l"(v));
    lo=__uint_as_float(l); hi=__uint_as_float(h);
}

// ================= GEMM (NT) =================
// C[m][n] = act(sum_k A[m][k]*B[n][k] + bias1[n] (+bias2[n]))
// BM=BN=128, BK=16, 256 threads, 8x8 thread tile, FFMA2, double-buffered.
// If hxs_init != nullptr, block (0,0) also resets the LSTM barrier and copies
// hxs -> g_h[0] (folded init so the LSTM is ncu launch index 5).
template<int ACT>
__global__ __launch_bounds__(256)
void gemm_nt(const float* __restrict__ A, const float* __restrict__ Bm,
             const float* __restrict__ bias1, const float* __restrict__ bias2,
             float* __restrict__ C, int K, int N, const float* hxs_init)
{
    __shared__ __align__(16) float As[2][16][132];
    __shared__ __align__(16) float Bs[2][16][132];
    const int tid = threadIdx.x;

    if (hxs_init && blockIdx.x==0 && blockIdx.y==0){
        if (tid==0){ g_arrive=0u; g_release=0u; }
        for (int i=tid;i<BB*HHD/4;i+=256)
            ((float4*)g_h[0])[i] = ((const float4*)hxs_init)[i];
    }

    const int tx = tid & 15, ty = tid >> 4;
    const float* Ab = A + (size_t)blockIdx.y * 128 * K;
    const float* Bb = Bm + (size_t)blockIdx.x * 128 * K;

    const int row0 = tid >> 2, c4 = (tid & 3) << 2;
    const int row1 = row0 + 64;

    unsigned long long acc[4][8];
#pragma unroll
    for (int i=0;i<4;i++)
#pragma unroll
        for (int j=0;j<8;j++) acc[i][j]=0ull;

    const int nk = K >> 4;
    {
        float4 a0 = __ldcg((const float4*)(Ab + (size_t)row0*K + c4));
        float4 b0 = __ldcg((const float4*)(Bb + (size_t)row0*K + c4));
        float4 a1 = __ldcg((const float4*)(Ab + (size_t)row1*K + c4));
        float4 b1 = __ldcg((const float4*)(Bb + (size_t)row1*K + c4));
        As[0][c4+0][row0]=a0.x; As[0][c4+1][row0]=a0.y; As[0][c4+2][row0]=a0.z; As[0][c4+3][row0]=a0.w;
        Bs[0][c4+0][row0]=b0.x; Bs[0][c4+1][row0]=b0.y; Bs[0][c4+2][row0]=b0.z; Bs[0][c4+3][row0]=b0.w;
        As[0][c4+0][row1]=a1.x; As[0][c4+1][row1]=a1.y; As[0][c4+2][row1]=a1.z; As[0][c4+3][row1]=a1.w;
        Bs[0][c4+0][row1]=b1.x; Bs[0][c4+1][row1]=b1.y; Bs[0][c4+2][row1]=b1.z; Bs[0][c4+3][row1]=b1.w;
    }
    __syncthreads();

    int buf = 0;
    for (int kt=0; kt<nk; kt++){
        float4 pa0, pb0, pa1, pb1;
        const bool more = (kt+1 < nk);
        if (more){
            int k0 = (kt+1) << 4;
            pa0 = __ldcg((const float4*)(Ab + (size_t)row0*K + k0 + c4));
            pb0 = __ldcg((const float4*)(Bb + (size_t)row0*K + k0 + c4));
            pa1 = __ldcg((const float4*)(Ab + (size_t)row1*K + k0 + c4));
            pb1 = __ldcg((const float4*)(Bb + (size_t)row1*K + k0 + c4));
        }
#pragma unroll
        for (int kk=0;kk<16;kk++){
            ulonglong2 ua = *(const ulonglong2*)&As[buf][kk][ty*8];
            ulonglong2 ub = *(const ulonglong2*)&As[buf][kk][ty*8+4];
            unsigned long long ap[4] = { ua.x, ua.y, ub.x, ub.y };
            float4 f0 = *(const float4*)&Bs[buf][kk][tx*8];
            float4 f1 = *(const float4*)&Bs[buf][kk][tx*8+4];
            unsigned long long bd[8] = { f2dup(f0.x),f2dup(f0.y),f2dup(f0.z),f2dup(f0.w),
                                         f2dup(f1.x),f2dup(f1.y),f2dup(f1.z),f2dup(f1.w) };
#pragma unroll
            for (int i=0;i<4;i++)
#pragma unroll
                for (int j=0;j<8;j++) fma2(acc[i][j], ap[i], bd[j]);
        }
        if (more){
            int nb = buf ^ 1;
            As[nb][c4+0][row0]=pa0.x; As[nb][c4+1][row0]=pa0.y; As[nb][c4+2][row0]=pa0.z; As[nb][c4+3][row0]=pa0.w;
            Bs[nb][c4+0][row0]=pb0.x; Bs[nb][c4+1][row0]=pb0.y; Bs[nb][c4+2][row0]=pb0.z; Bs[nb][c4+3][row0]=pb0.w;
            As[nb][c4+0][row1]=pa1.x; As[nb][c4+1][row1]=pa1.y; As[nb][c4+2][row1]=pa1.z; As[nb][c4+3][row1]=pa1.w;
            Bs[nb][c4+0][row1]=pb1.x; Bs[nb][c4+1][row1]=pb1.y; Bs[nb][c4+2][row1]=pb1.z; Bs[nb][c4+3][row1]=pb1.w;
            __syncthreads();
            buf = nb;
        }
    }

    const int colb = blockIdx.x*128 + tx*8;
    float bv[8];
#pragma unroll
    for (int j=0;j<8;j++) bv[j] = bias1[colb+j] + (bias2 ? bias2[colb+j] : 0.f);
    const size_t rowb = (size_t)blockIdx.y*128 + ty*8;
#pragma unroll
    for (int i=0;i<4;i++){
        float v0[8], v1[8];
#pragma unroll
        for (int j=0;j<8;j++){
            float x0,x1; unpack2(acc[i][j],x0,x1);
            x0+=bv[j]; x1+=bv[j];
            if (ACT==1){ x0 = x0/(1.f+expf(-x0)); x1 = x1/(1.f+expf(-x1)); }
            v0[j]=x0; v1[j]=x1;
        }
        float* c0 = C + (rowb + 2*i)*(size_t)N + colb;
        float* c1 = c0 + N;
        __stcg((float4*)(c0),   make_float4(v0[0],v0[1],v0[2],v0[3]));
        __stcg((float4*)(c0+4), make_float4(v0[4],v0[5],v0[6],v0[7]));
        __stcg((float4*)(c1),   make_float4(v1[0],v1[1],v1[2],v1[3]));
        __stcg((float4*)(c1+4), make_float4(v1[4],v1[5],v1[6],v1[7]));
    }
}

// ================= Persistent LSTM =================
// 128 blocks = 4 b-tiles(32 rows) x 32 h-tiles(16 h), 128 THREADS.
// Thread owns (1 h x 4 gates x 4 b-rows: bg+8j). Weight LDG traffic halved
// (1MB/CTA/step); h LDS conflict-free with 4-lane broadcast. c in registers;
// acq_rel grid barrier (no fences -> weights stay L1-resident).
#define HS_STRIDE 516
__global__ __launch_bounds__(128)
void lstm_kernel(const float* __restrict__ Whh, const float* __restrict__ cxs,
                 float* __restrict__ dout)
{
    extern __shared__ __align__(16) float smem[];
    float* hsm = smem;                        // 32 x 516 floats
    float* xsm = hsm + 32*HS_STRIDE;          // 32 x 64
    float* STb = xsm + 32*64;                 // 5 x 32 x 16
#define ST(a,r,q) STb[(((a)*32+(r))*16)+(q)]
    const int tid = threadIdx.x;              // 0..127
    const int b0 = (blockIdx.x & 3) * 32;
    const int hbase = (blockIdx.x >> 2) * 16;
    const int bg = tid & 7;                   // 0..7
    const int hloc = tid >> 3;                // 0..15
    const int h = hbase + hloc;

    const float* w0 = Whh + (size_t)(0*HHD + h)*HHD;
    const float* w1 = Whh + (size_t)(1*HHD + h)*HHD;
    const float* w2 = Whh + (size_t)(2*HHD + h)*HHD;
    const float* w3 = Whh + (size_t)(3*HHD + h)*HHD;

    float c[4];
#pragma unroll
    for (int j=0;j<4;j++) c[j] = cxs[(size_t)(b0+bg+8*j)*HHD + h];

    float* outb = g_enc1;
    float* gp1 = dout + OFF_IG;  float* gp2 = dout + OFF_FG;
    float* gp3 = dout + OFF_GG;  float* gp4 = dout + OFF_OG;

    for (int t=0;t<TT;t++){
        const float* hin = g_h[t&1];
        float* hnx = g_h[(t+1)&1];

        // stage h tile (32 x 512) = 4096 float4 by 128 threads
#pragma unroll
        for (int l=tid;l<4096;l+=128){
            int r = l>>7, cc = (l&127)<<2;
            float4 v = __ldcv((const float4*)(hin + (size_t)(b0+r)*HHD + cc));
            *(float4*)&hsm[r*HS_STRIDE + cc] = v;
        }
        // stage xg tile (32 rows x 4 gates x 16 h): 512 float4
#pragma unroll
        for (int l=tid;l<512;l+=128){
            int r = l>>4, rem = l&15, g = rem>>2, q4 = (rem&3)<<2;
            float4 v = __ldcg((const float4*)(g_xg + ((size_t)(b0+r)*TT + t)*G4 + (size_t)g*HHD + hbase + q4));
            *(float4*)&xsm[r*64 + g*16 + q4] = v;
        }
        __syncthreads();

        unsigned long long acc[4][4];
#pragma unroll
        for (int j=0;j<4;j++)
#pragma unroll
            for (int g=0;g<4;g++) acc[j][g]=0ull;

#pragma unroll 2
        for (int k=0;k<HHD;k+=4){
            ulonglong2 wa = __ldg((const ulonglong2*)(w0+k));
            ulonglong2 wb = __ldg((const ulonglong2*)(w1+k));
            ulonglong2 wc = __ldg((const ulonglong2*)(w2+k));
            ulonglong2 wd = __ldg((const ulonglong2*)(w3+k));
#pragma unroll
            for (int j=0;j<4;j++){
                ulonglong2 hj = *(const ulonglong2*)&hsm[(bg+8*j)*HS_STRIDE + k];
                fma2(acc[j][0],hj.x,wa.x); fma2(acc[j][0],hj.y,wa.y);
                fma2(acc[j][1],hj.x,wb.x); fma2(acc[j][1],hj.y,wb.y);
                fma2(acc[j][2],hj.x,wc.x); fma2(acc[j][2],hj.y,wc.y);
                fma2(acc[j][3],hj.x,wd.x); fma2(acc[j][3],hj.y,wd.y);
            }
        }

        float ho[4];
#pragma unroll
        for (int j=0;j<4;j++){
            int r = bg + 8*j;
            float s0,s1,s2,s3,x0,x1;
            unpack2(acc[j][0],x0,x1); s0 = x0+x1;
            unpack2(acc[j][1],x0,x1); s1 = x0+x1;
            unpack2(acc[j][2],x0,x1); s2 = x0+x1;
            unpack2(acc[j][3],x0,x1); s3 = x0+x1;
            float ig = sigf(s0 + xsm[r*64 + 0*16 + hloc]);
            float fg = sigf(s1 + xsm[r*64 + 1*16 + hloc]);
            float gg = tanhf(s2 + xsm[r*64 + 2*16 + hloc]);
            float og = sigf(s3 + xsm[r*64 + 3*16 + hloc]);
            c[j] = fg*c[j] + ig*gg;
            ho[j] = og*tanhf(c[j]);
            ST(0,r,hloc)=ho[j];
            ST(1,r,hloc)=ig; ST(2,r,hloc)=fg;
            ST(3,r,hloc)=gg; ST(4,r,hloc)=og;
        }
        __syncthreads();

        // h: 128 float4 slots; gates: 1024 float2 slots (gate sections of d_out
        // are only 8B-aligned: OFF_IG*4 == 8 mod 16). Streaming stores.
        for (int l=tid;l<1152;l+=128){
            if (l < 128){
                int r = l>>2, q4 = (l&3)<<2;
                float4 v = *(const float4*)&ST(0,r,q4);
                __stcg((float4*)(hnx + (size_t)(b0+r)*HHD + hbase + q4), v);
                __stcg((float4*)(outb + ((size_t)(b0+r)*TT + t)*HHD + hbase + q4), v);
            } else {
                int m = l - 128;
                int a = m >> 8;
                int r = (m >> 3) & 31;
                int q2 = (m & 7) << 1;
                float2 v = *(const float2*)&ST(a+1,r,q2);
                size_t base = ((size_t)(b0+r)*TT + t)*HHD + hbase + q2;
                float* gp = (a==0) ? gp1 : (a==1) ? gp2 : (a==2) ? gp3 : gp4;
                __stcg((float2*)(gp + base), v);
            }
        }

        if (t==TT-1){
#pragma unroll
            for (int j=0;j<4;j++){
                dout[OFF_HT + (size_t)(b0+bg+8*j)*HHD + h] = ho[j];
                dout[OFF_CT + (size_t)(b0+bg+8*j)*HHD + h] = c[j];
            }
        }

        __syncthreads();   // all stores (incl. hnx) issued before arrive
        if (tid==0){
            unsigned v;
            asm volatile("atom.acq_rel.gpu.global.add.u32 %0, [%1], %2;"
                         : "=r"(v) : "l"(&g_arrive), "r"(1u) : "memory");
            if (v == 127u){
                g_arrive = 0u;
                asm volatile("st.release.gpu.global.u32 [%0], %1;"
                             :: "l"(&g_release), "r"((unsigned)(t+1)) : "memory");
            } else {
                unsigned r;
                do {
                    asm volatile("ld.acquire.gpu.global.u32 %0, [%1];"
                                 : "=r"(r) : "l"(&g_release) : "memory");
                } while (r < (unsigned)(t+1));
            }
        }
        __syncthreads();
    }
#undef ST
}

__global__ __launch_bounds__(256)
void head_kernel(const float* __restrict__ Wa, const float* __restrict__ ba,
                 const float* __restrict__ Wc, const float* __restrict__ bc,
                 float* __restrict__ dout)
{
    __shared__ __align__(16) float xsr[16][516];
    const int tid = threadIdx.x;
    const size_t m0 = (size_t)blockIdx.x * 16;
    for (int l=tid;l<2048;l+=256){
        int r=l>>7, c4=(l&127)<<2;
        *(float4*)&xsr[r][c4] = *(const float4*)(g_enc1 + (m0+r)*HHD + c4);
    }
    __syncthreads();
    for (int o=tid;o<16*19;o+=256){
        int r=o/19, n=o-r*19;
        const float* wrow = (n<18) ? (Wa + (size_t)n*HHD) : Wc;
        float acc=0.f;
#pragma unroll 4
        for (int k=0;k<HHD;k+=4){
            float4 w = __ldg((const float4*)(wrow+k));
            float4 x = *(const float4*)&xsr[r][k];
            acc += x.x*w.x + x.y*w.y + x.z*w.z + x.w*w.w;
        }
        size_t m = m0 + r;
        if (n<18) dout[OFF_LOGITS + m*AA + n] = acc + ba[n];
        else      dout[OFF_VALUES + m] = acc + bc[0];
    }
}

__global__ __launch_bounds__(256)
void loss_partial()
{
    float s1=0.f, s2=0.f;
    const size_t n = (size_t)MM*HHD;
    for (size_t i=(size_t)blockIdx.x*256+threadIdx.x; i<n; i+=(size_t)LOSS_BLOCKS*256){
        float x = g_enc1[i];
        s1 += x*x;
        unsigned t = ((unsigned)(i>>9)) & 511u;
        if (t != 511u){ float d = g_enc1[i+512] - x; s2 += d*d; }
    }
    __shared__ double r1[256], r2[256];
    r1[threadIdx.x]=(double)s1; r2[threadIdx.x]=(double)s2;
    __syncthreads();
    for (int s=128;s>0;s>>=1){
        if (threadIdx.x<s){ r1[threadIdx.x]+=r1[threadIdx.x+s]; r2[threadIdx.x]+=r2[threadIdx.x+s]; }
        __syncthreads();
    }
    if (threadIdx.x==0){ g_part[0][blockIdx.x]=r1[0]; g_part[1][blockIdx.x]=r2[0]; }
}

__global__ void loss_final(float* __restrict__ dout)
{
    __shared__ double r1[256], r2[256];
    double s1=0.0, s2=0.0;
    for (int i=threadIdx.x;i<LOSS_BLOCKS;i+=256){ s1+=g_part[0][i]; s2+=g_part[1][i]; }
    r1[threadIdx.x]=s1; r2[threadIdx.x]=s2;
    __syncthreads();
    for (int s=128;s>0;s>>=1){
        if (threadIdx.x<s){ r1[threadIdx.x]+=r1[threadIdx.x+s]; r2[threadIdx.x]+=r2[threadIdx.x+s]; }
        __syncthreads();
    }
    if (threadIdx.x==0){
        dout[OFF_AR]  = (float)(r1[0] * (0.01 / ((double)MM * HHD)));
        dout[OFF_TAR] = (float)(r2[0] * (0.01 / ((double)BB * (TT-1) * HHD)));
    }
}

extern "C" void kernel_launch(void* const* d_in, const int* in_sizes, int n_in,
                              void* d_out, int out_size)
{
    const float* obs  = (const float*)d_in[0];
    const float* hxs  = (const float*)d_in[1];
    const float* cxs  = (const float*)d_in[2];
    const float* W1   = (const float*)d_in[3];
    const float* b1   = (const float*)d_in[4];
    const float* W2   = (const float*)d_in[5];
    const float* b2   = (const float*)d_in[6];
    const float* W_ih = (const float*)d_in[7];
    const float* W_hh = (const float*)d_in[8];
    const float* b_ih = (const float*)d_in[9];
    const float* b_hh = (const float*)d_in[10];
    const float* Wa   = (const float*)d_in[11];
    const float* ba   = (const float*)d_in[12];
    const float* Wc   = (const float*)d_in[13];
    const float* bc   = (const float*)d_in[14];
    float* dout = (float*)d_out;

    float* enc1; cudaGetSymbolAddress((void**)&enc1, g_enc1);
    float* enc2; cudaGetSymbolAddress((void**)&enc2, g_enc2);
    float* xg;   cudaGetSymbolAddress((void**)&xg,   g_xg);

    const int lstm_smem = (32*HS_STRIDE + 32*64 + 5*32*16) * (int)sizeof(float);
    cudaFuncSetAttribute(lstm_kernel, cudaFuncAttributeMaxDynamicSharedMemorySize, lstm_smem);

    // enc1 = silu(obs @ W1^T + b1); block(0,0) also does LSTM init (hxs copy + barrier reset)
    gemm_nt<1><<<dim3(ENC/128, MM/128), 256>>>(obs, W1, b1, nullptr, enc1, 128, ENC, hxs);
    // enc2 = silu(enc1 @ W2^T + b2)
    gemm_nt<1><<<dim3(ENC/128, MM/128), 256>>>(enc1, W2, b2, nullptr, enc2, ENC, ENC, nullptr);
    // xg = enc2 @ W_ih^T + b_ih + b_hh
    gemm_nt<0><<<dim3(G4/128, MM/128), 256>>>(enc2, W_ih, b_ih, b_hh, xg, ENC, G4, nullptr);

    lstm_kernel<<<128, 128, lstm_smem>>>(W_hh, cxs, dout);   // ncu -s 5 lands here
    head_kernel<<<MM/16, 256>>>(Wa, ba, Wc, bc, dout);
    loss_partial<<<LOSS_BLOCKS, 256>>>();
    loss_final<<<1, 256>>>(dout);
}

// round 11
// speedup vs baseline: 1.1841x; 1.1841x over previous
#include <cuda_runtime.h>
#include <math.h>

#define BB 128
#define TT 512
#define ENC 512
#define HHD 512
#define AA 18
#define MM (BB*TT)
#define G4 (4*HHD)

#define N_LOGITS ((size_t)MM*AA)
#define OFF_LOGITS ((size_t)0)
#define OFF_VALUES (N_LOGITS)
#define OFF_HT (OFF_VALUES + (size_t)MM)
#define OFF_CT (OFF_HT + (size_t)BB*HHD)
#define OFF_AR (OFF_CT + (size_t)BB*HHD)
#define OFF_TAR (OFF_AR + 1)
#define NGATE ((size_t)MM*HHD)
#define OFF_IG (OFF_TAR + 1)
#define OFF_FG (OFF_IG + NGATE)
#define OFF_GG (OFF_FG + NGATE)
#define OFF_OG (OFF_GG + NGATE)

__device__ __align__(16) float g_enc1[(size_t)MM*ENC];   // enc1; later reused as LSTM out (B,T,H)
__device__ __align__(16) float g_enc2[(size_t)MM*ENC];
__device__ __align__(16) float g_xg[(size_t)MM*G4];
__device__ __align__(16) float g_h[2][BB*HHD];
#define LOSS_BLOCKS 2048
__device__ double g_part[2][LOSS_BLOCKS];
__device__ unsigned g_arrive;
__device__ unsigned g_release;

__device__ __forceinline__ void fma2(unsigned long long& d, unsigned long long a, unsigned long long b){
    asm("fma.rn.f32x2 %0, %1, %2, %0;" : "+l"(d) : "l"(a), "l"(b));
}
__device__ __forceinline__ unsigned long long f2dup(float x){
    unsigned long long r; asm("mov.b64 %0, {%1, %1};" : "=l"(r) : "r"(__float_as_uint(x))); return r;
}
__device__ __forceinline__ unsigned long long f2pack(float lo, float hi){
    unsigned long long r; asm("mov.b64 %0, {%1, %2};" : "=l"(r) : "r"(__float_as_uint(lo)), "r"(__float_as_uint(hi))); return r;
}
__device__ __forceinline__ void unpack2(unsigned long long v, float& lo, float& hi){
    unsigned l,h; asm("mov.b64 {%0, %1}, %2;" : "=r"(l), "=r"(h) : "l"(v));
    lo=__uint_as_float(l); hi=__uint_as_float(h);
}

// ================= GEMM (NT) =================
// Unchanged from R8 (L1 97%, fma 64% - near its shape limit).
template<int ACT>
__global__ __launch_bounds__(256)
void gemm_nt(const float* __restrict__ A, const float* __restrict__ Bm,
             const float* __restrict__ bias1, const float* __restrict__ bias2,
             float* __restrict__ C, int K, int N, const float* hxs_init)
{
    __shared__ __align__(16) float As[2][16][132];
    __shared__ __align__(16) float Bs[2][16][132];
    const int tid = threadIdx.x;

    if (hxs_init && blockIdx.x==0 && blockIdx.y==0){
        if (tid==0){ g_arrive=0u; g_release=0u; }
        for (int i=tid;i<BB*HHD/4;i+=256)
            ((float4*)g_h[0])[i] = ((const float4*)hxs_init)[i];
    }

    const int tx = tid & 15, ty = tid >> 4;
    const float* Ab = A + (size_t)blockIdx.y * 128 * K;
    const float* Bb = Bm + (size_t)blockIdx.x * 128 * K;

    const int row0 = tid >> 2, c4 = (tid & 3) << 2;
    const int row1 = row0 + 64;

    unsigned long long acc[4][8];
#pragma unroll
    for (int i=0;i<4;i++)
#pragma unroll
        for (int j=0;j<8;j++) acc[i][j]=0ull;

    const int nk = K >> 4;
    {
        float4 a0 = __ldcg((const float4*)(Ab + (size_t)row0*K + c4));
        float4 b0 = __ldcg((const float4*)(Bb + (size_t)row0*K + c4));
        float4 a1 = __ldcg((const float4*)(Ab + (size_t)row1*K + c4));
        float4 b1 = __ldcg((const float4*)(Bb + (size_t)row1*K + c4));
        As[0][c4+0][row0]=a0.x; As[0][c4+1][row0]=a0.y; As[0][c4+2][row0]=a0.z; As[0][c4+3][row0]=a0.w;
        Bs[0][c4+0][row0]=b0.x; Bs[0][c4+1][row0]=b0.y; Bs[0][c4+2][row0]=b0.z; Bs[0][c4+3][row0]=b0.w;
        As[0][c4+0][row1]=a1.x; As[0][c4+1][row1]=a1.y; As[0][c4+2][row1]=a1.z; As[0][c4+3][row1]=a1.w;
        Bs[0][c4+0][row1]=b1.x; Bs[0][c4+1][row1]=b1.y; Bs[0][c4+2][row1]=b1.z; Bs[0][c4+3][row1]=b1.w;
    }
    __syncthreads();

    int buf = 0;
    for (int kt=0; kt<nk; kt++){
        float4 pa0, pb0, pa1, pb1;
        const bool more = (kt+1 < nk);
        if (more){
            int k0 = (kt+1) << 4;
            pa0 = __ldcg((const float4*)(Ab + (size_t)row0*K + k0 + c4));
            pb0 = __ldcg((const float4*)(Bb + (size_t)row0*K + k0 + c4));
            pa1 = __ldcg((const float4*)(Ab + (size_t)row1*K + k0 + c4));
            pb1 = __ldcg((const float4*)(Bb + (size_t)row1*K + k0 + c4));
        }
#pragma unroll
        for (int kk=0;kk<16;kk++){
            ulonglong2 ua = *(const ulonglong2*)&As[buf][kk][ty*8];
            ulonglong2 ub = *(const ulonglong2*)&As[buf][kk][ty*8+4];
            unsigned long long ap[4] = { ua.x, ua.y, ub.x, ub.y };
            float4 f0 = *(const float4*)&Bs[buf][kk][tx*8];
            float4 f1 = *(const float4*)&Bs[buf][kk][tx*8+4];
            unsigned long long bd[8] = { f2dup(f0.x),f2dup(f0.y),f2dup(f0.z),f2dup(f0.w),
                                         f2dup(f1.x),f2dup(f1.y),f2dup(f1.z),f2dup(f1.w) };
#pragma unroll
            for (int i=0;i<4;i++)
#pragma unroll
                for (int j=0;j<8;j++) fma2(acc[i][j], ap[i], bd[j]);
        }
        if (more){
            int nb = buf ^ 1;
            As[nb][c4+0][row0]=pa0.x; As[nb][c4+1][row0]=pa0.y; As[nb][c4+2][row0]=pa0.z; As[nb][c4+3][row0]=pa0.w;
            Bs[nb][c4+0][row0]=pb0.x; Bs[nb][c4+1][row0]=pb0.y; Bs[nb][c4+2][row0]=pb0.z; Bs[nb][c4+3][row0]=pb0.w;
            As[nb][c4+0][row1]=pa1.x; As[nb][c4+1][row1]=pa1.y; As[nb][c4+2][row1]=pa1.z; As[nb][c4+3][row1]=pa1.w;
            Bs[nb][c4+0][row1]=pb1.x; Bs[nb][c4+1][row1]=pb1.y; Bs[nb][c4+2][row1]=pb1.z; Bs[nb][c4+3][row1]=pb1.w;
            __syncthreads();
            buf = nb;
        }
    }

    const int colb = blockIdx.x*128 + tx*8;
    float bv[8];
#pragma unroll
    for (int j=0;j<8;j++) bv[j] = bias1[colb+j] + (bias2 ? bias2[colb+j] : 0.f);
    const size_t rowb = (size_t)blockIdx.y*128 + ty*8;
#pragma unroll
    for (int i=0;i<4;i++){
        float v0[8], v1[8];
#pragma unroll
        for (int j=0;j<8;j++){
            float x0,x1; unpack2(acc[i][j],x0,x1);
            x0+=bv[j]; x1+=bv[j];
            if (ACT==1){ x0 = x0/(1.f+expf(-x0)); x1 = x1/(1.f+expf(-x1)); }
            v0[j]=x0; v1[j]=x1;
        }
        float* c0 = C + (rowb + 2*i)*(size_t)N + colb;
        float* c1 = c0 + N;
        __stcg((float4*)(c0),   make_float4(v0[0],v0[1],v0[2],v0[3]));
        __stcg((float4*)(c0+4), make_float4(v0[4],v0[5],v0[6],v0[7]));
        __stcg((float4*)(c1),   make_float4(v1[0],v1[1],v1[2],v1[3]));
        __stcg((float4*)(c1+4), make_float4(v1[4],v1[5],v1[6],v1[7]));
    }
}

// ================= Persistent LSTM (weights in registers) =================
// 128 CTAs = 4 b-tiles(32 rows) x 32 h-tiles(16 h). 256 threads =
// (16 h x 4 gates x 4 k-slices). Each thread holds its 128-float W_hh slice
// in 64 u64 registers (loaded once). Phase1: per-row FFMA2 partial dots ->
// smem gsum (bank-exact conflict-free). Phase2: 128 cells/..., grouped-rcp
// activations (7 MUFU/cell instead of 10). acq_rel grid barrier, no fences.
#define HROW 528              // 512 + 4x4 gaps: slice ks starts at ks*132
__global__ __launch_bounds__(256, 1)
void lstm_kernel(const float* __restrict__ Whh, const float* __restrict__ cxs,
                 float* __restrict__ dout)
{
    extern __shared__ __align__(16) float smem[];
    float* hsm  = smem;                       // 32 x 528            (67,584B)
    float* xsm  = hsm + 32*HROW;              // 32 x 64             (8,192B)
    float* gsum = xsm + 32*64;                // 512 slots x 17      (34,816B)
    float* STb  = gsum + 512*17;              // 5 x 32 x 16         (10,240B)
#define ST(a,r,q) STb[(((a)*32+(r))*16)+(q)]
    const int tid   = threadIdx.x;
    const int b0    = (blockIdx.x & 3) * 32;
    const int hbase = (blockIdx.x >> 2) * 16;
    const int ks    = tid & 3;
    const int gate  = (tid >> 2) & 3;
    const int hloc  = tid >> 4;               // 0..15

    // ---- load weight slice into registers (once) ----
    unsigned long long w[64];
    {
        const float* wp = Whh + ((size_t)(gate*HHD + hbase + hloc))*HHD + ks*128;
#pragma unroll
        for (int j=0;j<32;j++){
            float4 v = __ldg((const float4*)(wp + j*4));
            w[2*j]   = f2pack(v.x, v.y);
            w[2*j+1] = f2pack(v.z, v.w);
        }
    }

    // ---- phase2 cell ownership: cells tid and tid+256 ----
    const int rA = tid >> 4,  hlA = tid & 15;       // rows 0..15
    const int rB = rA + 16;                          // rows 16..31
    float cA = cxs[(size_t)(b0+rA)*HHD + hbase + hlA];
    float cB = cxs[(size_t)(b0+rB)*HHD + hbase + hlA];

    float* outb = g_enc1;
    float* gp1 = dout + OFF_IG;  float* gp2 = dout + OFF_FG;
    float* gp3 = dout + OFF_GG;  float* gp4 = dout + OFF_OG;

    for (int t=0;t<TT;t++){
        const float* hin = g_h[t&1];
        float* hnx = g_h[(t+1)&1];

        // stage h tile (32x512) with gap layout: pos = r*528 + k + (k>>7)*4
#pragma unroll
        for (int l=tid;l<4096;l+=256){
            int r = l>>7, f4 = l&127;
            float4 v = __ldcv((const float4*)(hin + (size_t)(b0+r)*HHD + f4*4));
            *(float4*)&hsm[r*HROW + f4*4 + (f4>>5)*4] = v;
        }
        // stage xg tile (32 rows x 4 gates x 16 h)
#pragma unroll
        for (int l=tid;l<512;l+=256){
            int r = l>>4, rem = l&15, g = rem>>2, q4 = (rem&3)<<2;
            float4 v = __ldcg((const float4*)(g_xg + ((size_t)(b0+r)*TT + t)*G4 + (size_t)g*HHD + hbase + q4));
            *(float4*)&xsm[r*64 + g*16 + q4] = v;
        }
        __syncthreads();

        // ---- phase 1: partial dot per (row, gate, ks) ----
#pragma unroll 1
        for (int r=0;r<32;r++){
            const float* hp = hsm + r*HROW + ks*132;
            unsigned long long a0=0ull,a1=0ull,a2=0ull,a3=0ull;
#pragma unroll
            for (int j=0;j<32;j+=2){
                ulonglong2 h0 = *(const ulonglong2*)(hp + j*4);
                ulonglong2 h1 = *(const ulonglong2*)(hp + j*4 + 4);
                fma2(a0, w[2*j],   h0.x);
                fma2(a1, w[2*j+1], h0.y);
                fma2(a2, w[2*j+2], h1.x);
                fma2(a3, w[2*j+3], h1.y);
            }
            float x0,x1,y0,y1,z0,z1,u0,u1;
            unpack2(a0,x0,x1); unpack2(a1,y0,y1);
            unpack2(a2,z0,z1); unpack2(a3,u0,u1);
            gsum[(r*16 + gate*4 + ks)*17 + hloc] = ((x0+x1)+(y0+y1)) + ((z0+z1)+(u0+u1));
        }
        __syncthreads();

        // ---- phase 2: activations for 2 cells ----
        float hoA, hoB;
#pragma unroll
        for (int cell=0; cell<2; cell++){
            int r  = cell ? rB : rA;
            float pre[4];
#pragma unroll
            for (int g=0; g<4; g++){
                const float* gp = gsum + (r*16 + g*4)*17 + hlA;
                float s = (gp[0] + gp[17]) + (gp[34] + gp[51]);
                pre[g] = s + xsm[r*64 + g*16 + hlA];
            }
            // grouped reciprocals: 4 denominators, one division
            float ei = expf(-pre[0]);
            float ef = expf(-pre[1]);
            float eg = expf(-2.f*pre[2]);
            float eo = expf(-pre[3]);
            float d0 = 1.f+ei, d1 = 1.f+ef, d2 = 1.f+eg, d3 = 1.f+eo;
            float p01 = d0*d1, p23 = d2*d3;
            float rp = 1.f/(p01*p23);
            float ig = rp*d1*p23;            // 1/d0
            float fg = rp*d0*p23;            // 1/d1
            float gg = (1.f-eg)*(rp*p01*d3); // tanh(pre_g)
            float og = rp*p01*d2;            // 1/d3
            float cc = cell ? cB : cA;
            cc = fg*cc + ig*gg;
            float ec = expf(-2.f*cc);
            float tc = (1.f-ec)/(1.f+ec);
            float ho = og*tc;
            if (cell){ cB = cc; hoB = ho; } else { cA = cc; hoA = ho; }
            ST(0,r,hlA)=ho;
            ST(1,r,hlA)=ig; ST(2,r,hlA)=fg;
            ST(3,r,hlA)=gg; ST(4,r,hlA)=og;
        }
        __syncthreads();

        // ---- store out: h float4, gates float2 (d_out gate base is 8B-aligned) ----
        for (int l=tid;l<1152;l+=256){
            if (l < 128){
                int r = l>>2, q4 = (l&3)<<2;
                float4 v = *(const float4*)&ST(0,r,q4);
                __stcg((float4*)(hnx + (size_t)(b0+r)*HHD + hbase + q4), v);
                __stcg((float4*)(outb + ((size_t)(b0+r)*TT + t)*HHD + hbase + q4), v);
            } else {
                int m = l - 128;
                int a = m >> 8;
                int r = (m >> 3) & 31;
                int q2 = (m & 7) << 1;
                float2 v = *(const float2*)&ST(a+1,r,q2);
                size_t base = ((size_t)(b0+r)*TT + t)*HHD + hbase + q2;
                float* gp = (a==0) ? gp1 : (a==1) ? gp2 : (a==2) ? gp3 : gp4;
                __stcg((float2*)(gp + base), v);
            }
        }

        if (t==TT-1){
            dout[OFF_HT + (size_t)(b0+rA)*HHD + hbase + hlA] = hoA;
            dout[OFF_HT + (size_t)(b0+rB)*HHD + hbase + hlA] = hoB;
            dout[OFF_CT + (size_t)(b0+rA)*HHD + hbase + hlA] = cA;
            dout[OFF_CT + (size_t)(b0+rB)*HHD + hbase + hlA] = cB;
        }

        __syncthreads();
        if (tid==0){
            unsigned v;
            asm volatile("atom.acq_rel.gpu.global.add.u32 %0, [%1], %2;"
                         : "=r"(v) : "l"(&g_arrive), "r"(1u) : "memory");
            if (v == 127u){
                g_arrive = 0u;
                asm volatile("st.release.gpu.global.u32 [%0], %1;"
                             :: "l"(&g_release), "r"((unsigned)(t+1)) : "memory");
            } else {
                unsigned r;
                do {
                    asm volatile("ld.acquire.gpu.global.u32 %0, [%1];"
                                 : "=r"(r) : "l"(&g_release) : "memory");
                } while (r < (unsigned)(t+1));
            }
        }
        __syncthreads();
    }
#undef ST
}

__global__ __launch_bounds__(256)
void head_kernel(const float* __restrict__ Wa, const float* __restrict__ ba,
                 const float* __restrict__ Wc, const float* __restrict__ bc,
                 float* __restrict__ dout)
{
    __shared__ __align__(16) float xsr[16][516];
    const int tid = threadIdx.x;
    const size_t m0 = (size_t)blockIdx.x * 16;
    for (int l=tid;l<2048;l+=256){
        int r=l>>7, c4=(l&127)<<2;
        *(float4*)&xsr[r][c4] = *(const float4*)(g_enc1 + (m0+r)*HHD + c4);
    }
    __syncthreads();
    for (int o=tid;o<16*19;o+=256){
        int r=o/19, n=o-r*19;
        const float* wrow = (n<18) ? (Wa + (size_t)n*HHD) : Wc;
        float acc=0.f;
#pragma unroll 4
        for (int k=0;k<HHD;k+=4){
            float4 w = __ldg((const float4*)(wrow+k));
            float4 x = *(const float4*)&xsr[r][k];
            acc += x.x*w.x + x.y*w.y + x.z*w.z + x.w*w.w;
        }
        size_t m = m0 + r;
        if (n<18) dout[OFF_LOGITS + m*AA + n] = acc + ba[n];
        else      dout[OFF_VALUES + m] = acc + bc[0];
    }
}

__global__ __launch_bounds__(256)
void loss_partial()
{
    float s1=0.f, s2=0.f;
    const size_t n = (size_t)MM*HHD;
    for (size_t i=(size_t)blockIdx.x*256+threadIdx.x; i<n; i+=(size_t)LOSS_BLOCKS*256){
        float x = g_enc1[i];
        s1 += x*x;
        unsigned t = ((unsigned)(i>>9)) & 511u;
        if (t != 511u){ float d = g_enc1[i+512] - x; s2 += d*d; }
    }
    __shared__ double r1[256], r2[256];
    r1[threadIdx.x]=(double)s1; r2[threadIdx.x]=(double)s2;
    __syncthreads();
    for (int s=128;s>0;s>>=1){
        if (threadIdx.x<s){ r1[threadIdx.x]+=r1[threadIdx.x+s]; r2[threadIdx.x]+=r2[threadIdx.x+s]; }
        __syncthreads();
    }
    if (threadIdx.x==0){ g_part[0][blockIdx.x]=r1[0]; g_part[1][blockIdx.x]=r2[0]; }
}

__global__ void loss_final(float* __restrict__ dout)
{
    __shared__ double r1[256], r2[256];
    double s1=0.0, s2=0.0;
    for (int i=threadIdx.x;i<LOSS_BLOCKS;i+=256){ s1+=g_part[0][i]; s2+=g_part[1][i]; }
    r1[threadIdx.x]=s1; r2[threadIdx.x]=s2;
    __syncthreads();
    for (int s=128;s>0;s>>=1){
        if (threadIdx.x<s){ r1[threadIdx.x]+=r1[threadIdx.x+s]; r2[threadIdx.x]+=r2[threadIdx.x+s]; }
        __syncthreads();
    }
    if (threadIdx.x==0){
        dout[OFF_AR]  = (float)(r1[0] * (0.01 / ((double)MM * HHD)));
        dout[OFF_TAR] = (float)(r2[0] * (0.01 / ((double)BB * (TT-1) * HHD)));
    }
}

extern "C" void kernel_launch(void* const* d_in, const int* in_sizes, int n_in,
                              void* d_out, int out_size)
{
    const float* obs  = (const float*)d_in[0];
    const float* hxs  = (const float*)d_in[1];
    const float* cxs  = (const float*)d_in[2];
    const float* W1   = (const float*)d_in[3];
    const float* b1   = (const float*)d_in[4];
    const float* W2   = (const float*)d_in[5];
    const float* b2   = (const float*)d_in[6];
    const float* W_ih = (const float*)d_in[7];
    const float* W_hh = (const float*)d_in[8];
    const float* b_ih = (const float*)d_in[9];
    const float* b_hh = (const float*)d_in[10];
    const float* Wa   = (const float*)d_in[11];
    const float* ba   = (const float*)d_in[12];
    const float* Wc   = (const float*)d_in[13];
    const float* bc   = (const float*)d_in[14];
    float* dout = (float*)d_out;

    float* enc1; cudaGetSymbolAddress((void**)&enc1, g_enc1);
    float* enc2; cudaGetSymbolAddress((void**)&enc2, g_enc2);
    float* xg;   cudaGetSymbolAddress((void**)&xg,   g_xg);

    const int lstm_smem = (32*HROW + 32*64 + 512*17 + 5*32*16) * (int)sizeof(float);
    cudaFuncSetAttribute(lstm_kernel, cudaFuncAttributeMaxDynamicSharedMemorySize, lstm_smem);

    // enc1 = silu(obs @ W1^T + b1); block(0,0) also does LSTM init
    gemm_nt<1><<<dim3(ENC/128, MM/128), 256>>>(obs, W1, b1, nullptr, enc1, 128, ENC, hxs);
    // enc2 = silu(enc1 @ W2^T + b2)
    gemm_nt<1><<<dim3(ENC/128, MM/128), 256>>>(enc1, W2, b2, nullptr, enc2, ENC, ENC, nullptr);
    // xg = enc2 @ W_ih^T + b_ih + b_hh
    gemm_nt<0><<<dim3(G4/128, MM/128), 256>>>(enc2, W_ih, b_ih, b_hh, xg, ENC, G4, nullptr);

    lstm_kernel<<<128, 256, lstm_smem>>>(W_hh, cxs, dout);   // ncu -s 5 lands here
    head_kernel<<<MM/16, 256>>>(Wa, ba, Wc, bc, dout);
    loss_partial<<<LOSS_BLOCKS, 256>>>();
    loss_final<<<1, 256>>>(dout);
}